// round 1
// baseline (speedup 1.0000x reference)
#include <cuda_runtime.h>
#include <cstdint>

// LightGCN_79044578115987
// Inputs (metadata order):
//   d_in[0] adj_rows  int32  [10,000,000]
//   d_in[1] adj_cols  int32  [10,000,000]
//   d_in[2] adj_vals  f32    [10,000,000]
//   d_in[3] user_emb  f32    [100000, 64]
//   d_in[4] item_emb  f32    [50000, 64]
//   d_in[5] brand_emb f32    [1000, 64]
// Output: [final_user | final_item | final_brand | user_emb | item_emb] f32
//         = [ (B0+B1+B2+B3)*0.25 over 151000x64 | user_emb | item_emb ]

#define NU 100000
#define NI 50000
#define NB 1000
#define NN (NU + NI + NB)      // 151000 nodes
#define DV 16                  // float4 per node row (64 floats)
#define NELT (NN * DV)         // float4 elements per buffer = 2,416,000

// 4 ping buffers: B0 = ego^0 (concat), B1..B3 = layer outputs. ~155 MB static.
__device__ float4 g_buf[4][NELT];

__global__ void k_init(const float4* __restrict__ u,
                       const float4* __restrict__ it,
                       const float4* __restrict__ b,
                       float4* __restrict__ out) {
    int idx = blockIdx.x * blockDim.x + threadIdx.x;
    if (idx >= NELT) return;
    float4 v;
    if (idx < NU * DV)               v = u[idx];
    else if (idx < (NU + NI) * DV)   v = it[idx - NU * DV];
    else                             v = b[idx - (NU + NI) * DV];
    g_buf[0][idx] = v;
    float4 z = make_float4(0.f, 0.f, 0.f, 0.f);
    g_buf[1][idx] = z;
    g_buf[2][idx] = z;
    g_buf[3][idx] = z;
    // Passthrough tail of the output: [user_emb | item_emb].
    // For idx < (NU+NI)*DV, v is exactly that concat.
    if (idx < (NU + NI) * DV) out[NELT + idx] = v;
}

// Edge-parallel SpMM: dst[row] += val * src[col], 16 threads per edge,
// float4 per thread, vectorized f32 reduction (red.global.add.v4.f32).
__global__ void k_spmm(const int*   __restrict__ rows,
                       const int*   __restrict__ cols,
                       const float* __restrict__ vals,
                       int src_i, int dst_i, int n_edges) {
    long long t = (long long)blockIdx.x * blockDim.x + threadIdx.x;
    long long e = t >> 4;
    if (e >= (long long)n_edges) return;
    int lane = (int)(t & 15);

    int   r = __ldg(rows + e);
    int   c = __ldg(cols + e);
    float v = __ldg(vals + e);

    float4 x = __ldg(&g_buf[src_i][(long long)c * DV + lane]);
    float4* p = &g_buf[dst_i][(long long)r * DV + lane];
    asm volatile("red.global.add.v4.f32 [%0], {%1, %2, %3, %4};"
                 :: "l"(p),
                    "f"(x.x * v), "f"(x.y * v), "f"(x.z * v), "f"(x.w * v)
                 : "memory");
}

__global__ void k_final(float4* __restrict__ out) {
    int idx = blockIdx.x * blockDim.x + threadIdx.x;
    if (idx >= NELT) return;
    float4 a = g_buf[0][idx];
    float4 b = g_buf[1][idx];
    float4 c = g_buf[2][idx];
    float4 d = g_buf[3][idx];
    out[idx] = make_float4((a.x + b.x + c.x + d.x) * 0.25f,
                           (a.y + b.y + c.y + d.y) * 0.25f,
                           (a.z + b.z + c.z + d.z) * 0.25f,
                           (a.w + b.w + c.w + d.w) * 0.25f);
}

extern "C" void kernel_launch(void* const* d_in, const int* in_sizes, int n_in,
                              void* d_out, int out_size) {
    const int*    rows = (const int*)  d_in[0];
    const int*    cols = (const int*)  d_in[1];
    const float*  vals = (const float*)d_in[2];
    const float4* u    = (const float4*)d_in[3];
    const float4* it   = (const float4*)d_in[4];
    const float4* b    = (const float4*)d_in[5];
    float4* out = (float4*)d_out;

    const int n_edges = in_sizes[0];
    const int THR = 256;

    int init_blocks = (NELT + THR - 1) / THR;
    k_init<<<init_blocks, THR>>>(u, it, b, out);

    long long tot = (long long)n_edges * DV;
    int spmm_blocks = (int)((tot + THR - 1) / THR);
    k_spmm<<<spmm_blocks, THR>>>(rows, cols, vals, 0, 1, n_edges);
    k_spmm<<<spmm_blocks, THR>>>(rows, cols, vals, 1, 2, n_edges);
    k_spmm<<<spmm_blocks, THR>>>(rows, cols, vals, 2, 3, n_edges);

    k_final<<<init_blocks, THR>>>(out);
}

// round 2
// speedup vs baseline: 2.3019x; 2.3019x over previous
#include <cuda_runtime.h>
#include <cstdint>

// LightGCN_79044578115987 — CSR-based, atomic-free SpMM layers.
// Inputs: adj_rows i32[10M], adj_cols i32[10M], adj_vals f32[10M],
//         user_emb f32[100000,64], item_emb f32[50000,64], brand_emb f32[1000,64]
// Output: [ (B0+B1+B2+B3)*0.25 over 151000x64 | user_emb | item_emb ]

#define NU 100000
#define NI 50000
#define NB 1000
#define NN (NU + NI + NB)          // 151000
#define DV 16                      // float4 per node row
#define NELT (NN * DV)             // 2,416,000 float4
#define MAXE 10000000
#define SCAN_T 1024
#define NBLK ((NN + SCAN_T - 1) / SCAN_T)   // 148

__device__ float4 g_buf[4][NELT];          // ego^0..ego^3
__device__ int2   g_edge[MAXE];            // CSR-ordered (col, val_bits)
__device__ int    g_cnt[NN];
__device__ int    g_off[NN + 1];
__device__ int    g_cur[NN];
__device__ int    g_bsum[NBLK];

// ---------------- init: fill B0 = concat(embs), passthrough output tail ----
__global__ void k_init(const float4* __restrict__ u,
                       const float4* __restrict__ it,
                       const float4* __restrict__ b,
                       float4* __restrict__ out) {
    int idx = blockIdx.x * blockDim.x + threadIdx.x;
    if (idx >= NELT) return;
    float4 v;
    if (idx < NU * DV)               v = u[idx];
    else if (idx < (NU + NI) * DV)   v = it[idx - NU * DV];
    else                             v = b[idx - (NU + NI) * DV];
    g_buf[0][idx] = v;
    if (idx < (NU + NI) * DV) out[NELT + idx] = v;   // [user_emb | item_emb]
}

// ---------------- CSR build ----------------
__global__ void k_zero() {
    int idx = blockIdx.x * blockDim.x + threadIdx.x;
    if (idx < NN) g_cnt[idx] = 0;
}

__global__ void k_hist(const int* __restrict__ rows, int n_edges) {
    int e = blockIdx.x * blockDim.x + threadIdx.x;
    if (e >= n_edges) return;
    atomicAdd(&g_cnt[__ldcs(rows + e)], 1);
}

__global__ void k_scan1() {
    __shared__ int s[SCAN_T];
    int t = threadIdx.x;
    int idx = blockIdx.x * SCAN_T + t;
    int v = (idx < NN) ? g_cnt[idx] : 0;
    s[t] = v;
    __syncthreads();
    #pragma unroll
    for (int d = 1; d < SCAN_T; d <<= 1) {
        int add = (t >= d) ? s[t - d] : 0;
        __syncthreads();
        s[t] += add;
        __syncthreads();
    }
    if (idx < NN) g_off[idx] = s[t] - v;             // block-local exclusive
    if (t == SCAN_T - 1) g_bsum[blockIdx.x] = s[t];  // block total
}

__global__ void k_scan2() {
    __shared__ int s[256];
    int t = threadIdx.x;
    int v = (t < NBLK) ? g_bsum[t] : 0;
    s[t] = v;
    __syncthreads();
    #pragma unroll
    for (int d = 1; d < 256; d <<= 1) {
        int add = (t >= d) ? s[t - d] : 0;
        __syncthreads();
        s[t] += add;
        __syncthreads();
    }
    if (t < NBLK) g_bsum[t] = s[t] - v;              // exclusive block offsets
}

__global__ void k_scan3(int n_edges) {
    int idx = blockIdx.x * blockDim.x + threadIdx.x;
    if (idx < NN) {
        int o = g_off[idx] + g_bsum[idx / SCAN_T];
        g_off[idx] = o;
        g_cur[idx] = o;
    }
    if (idx == 0) g_off[NN] = n_edges;
}

__global__ void k_scatter(const int*   __restrict__ rows,
                          const int*   __restrict__ cols,
                          const float* __restrict__ vals,
                          int n_edges) {
    int e = blockIdx.x * blockDim.x + threadIdx.x;
    if (e >= n_edges) return;
    int r = __ldcs(rows + e);
    int c = __ldcs(cols + e);
    float v = __ldcs(vals + e);
    int pos = atomicAdd(&g_cur[r], 1);
    g_edge[pos] = make_int2(c, __float_as_int(v));
}

// ---------------- CSR SpMM: one warp per node, float2 per lane -------------
__global__ void __launch_bounds__(256) k_spmm_csr(int src_i, int dst_i) {
    int warp = (blockIdx.x * blockDim.x + threadIdx.x) >> 5;
    int lane = threadIdx.x & 31;
    if (warp >= NN) return;
    int s = g_off[warp];
    int e = g_off[warp + 1];
    const float2* __restrict__ src = (const float2*)g_buf[src_i];
    float2 acc = make_float2(0.f, 0.f);
    #pragma unroll 4
    for (int i = s; i < e; ++i) {
        int2 cv = __ldcs(&g_edge[i]);                 // warp-broadcast, evict-first
        float v = __int_as_float(cv.y);
        float2 x = __ldg(&src[(unsigned)cv.x * 32u + (unsigned)lane]);
        acc.x = fmaf(v, x.x, acc.x);
        acc.y = fmaf(v, x.y, acc.y);
    }
    ((float2*)g_buf[dst_i])[(unsigned)warp * 32u + (unsigned)lane] = acc;
}

// ---------------- finalize: out = (B0+B1+B2+B3) * 0.25 ---------------------
__global__ void k_final(float4* __restrict__ out) {
    int idx = blockIdx.x * blockDim.x + threadIdx.x;
    if (idx >= NELT) return;
    float4 a = g_buf[0][idx];
    float4 b = g_buf[1][idx];
    float4 c = g_buf[2][idx];
    float4 d = g_buf[3][idx];
    out[idx] = make_float4((a.x + b.x + c.x + d.x) * 0.25f,
                           (a.y + b.y + c.y + d.y) * 0.25f,
                           (a.z + b.z + c.z + d.z) * 0.25f,
                           (a.w + b.w + c.w + d.w) * 0.25f);
}

extern "C" void kernel_launch(void* const* d_in, const int* in_sizes, int n_in,
                              void* d_out, int out_size) {
    const int*    rows = (const int*)  d_in[0];
    const int*    cols = (const int*)  d_in[1];
    const float*  vals = (const float*)d_in[2];
    const float4* u    = (const float4*)d_in[3];
    const float4* it   = (const float4*)d_in[4];
    const float4* b    = (const float4*)d_in[5];
    float4* out = (float4*)d_out;

    const int n_edges = in_sizes[0];
    const int THR = 256;

    int nelt_blocks = (NELT + THR - 1) / THR;
    int edge_blocks = (n_edges + THR - 1) / THR;
    int node_blocks = (NN + THR - 1) / THR;

    k_init<<<nelt_blocks, THR>>>(u, it, b, out);

    // CSR build (amortized over 3 layers)
    k_zero<<<node_blocks, THR>>>();
    k_hist<<<edge_blocks, THR>>>(rows, n_edges);
    k_scan1<<<NBLK, SCAN_T>>>();
    k_scan2<<<1, 256>>>();
    k_scan3<<<node_blocks, THR>>>(n_edges);
    k_scatter<<<edge_blocks, THR>>>(rows, cols, vals, n_edges);

    // 3 atomic-free SpMM layers
    int spmm_blocks = (NN * 32 + THR - 1) / THR;
    k_spmm_csr<<<spmm_blocks, THR>>>(0, 1);
    k_spmm_csr<<<spmm_blocks, THR>>>(1, 2);
    k_spmm_csr<<<spmm_blocks, THR>>>(2, 3);

    k_final<<<nelt_blocks, THR>>>(out);
}